// round 1
// baseline (speedup 1.0000x reference)
#include <cuda_runtime.h>
#include <math.h>

#define T_STEPS 128
#define BATCH   32
#define HIDDEN  1024
#define GATES   4096     // 4*HIDDEN
#define NCLS    32000
#define M_ALL   4096     // T_STEPS*BATCH

// ---------------- scratch (device globals; no allocation) ----------------
__device__ float g_XG[(size_t)M_ALL * GATES];   // 64 MB: x@W_x + b, all steps
__device__ float g_HS[(size_t)M_ALL * HIDDEN];  // 16 MB: h history
__device__ float g_h[2][BATCH * HIDDEN];        // double-buffered h state
__device__ float g_c[BATCH * HIDDEN];           // c state

// ---------------- init: zero h0, c0 (must run every call) ----------------
__global__ void init_state_kernel() {
    int i = blockIdx.x * blockDim.x + threadIdx.x;
    if (i < BATCH * HIDDEN) {
        g_h[0][i] = 0.0f;
        g_c[i] = 0.0f;
    }
}

// ---------------- GEMM 1: XG = emb[ids] @ Wx + b  (M=4096,N=4096,K=1024) --
// 128x128x8 tile, 8x8 per thread, 256 threads.
__global__ void gemm_embed_kernel(const int* __restrict__ ids,
                                  const float* __restrict__ emb,
                                  const float* __restrict__ Wx,
                                  const float* __restrict__ bias) {
    __shared__ __align__(16) float As[8][128];
    __shared__ __align__(16) float Bs[8][128];
    __shared__ int ids_s[128];

    const int tid = threadIdx.x;
    const int bm = blockIdx.y * 128;
    const int bn = blockIdx.x * 128;

    if (tid < 128) ids_s[tid] = ids[bm + tid];
    __syncthreads();

    const int arow = tid >> 1;          // 0..127
    const int acol = (tid & 1) * 4;     // 0 or 4
    const int brow = tid >> 5;          // 0..7
    const int bcol = (tid & 31) * 4;    // 0..124
    const int tx = tid & 15, ty = tid >> 4;

    const float* Arow = emb + (size_t)ids_s[arow] * HIDDEN;

    float acc[8][8];
#pragma unroll
    for (int i = 0; i < 8; i++)
#pragma unroll
        for (int j = 0; j < 8; j++) acc[i][j] = 0.0f;

    for (int k0 = 0; k0 < HIDDEN; k0 += 8) {
        float4 av = *(const float4*)(Arow + k0 + acol);
        As[acol + 0][arow] = av.x;
        As[acol + 1][arow] = av.y;
        As[acol + 2][arow] = av.z;
        As[acol + 3][arow] = av.w;
        float4 bv = *(const float4*)(Wx + (size_t)(k0 + brow) * GATES + bn + bcol);
        *(float4*)&Bs[brow][bcol] = bv;
        __syncthreads();
#pragma unroll
        for (int kk = 0; kk < 8; kk++) {
            float a[8], b[8];
#pragma unroll
            for (int i = 0; i < 8; i++) a[i] = As[kk][ty * 8 + i];
#pragma unroll
            for (int j = 0; j < 8; j++) b[j] = Bs[kk][tx * 8 + j];
#pragma unroll
            for (int i = 0; i < 8; i++)
#pragma unroll
                for (int j = 0; j < 8; j++) acc[i][j] += a[i] * b[j];
        }
        __syncthreads();
    }

#pragma unroll
    for (int i = 0; i < 8; i++) {
        int row = bm + ty * 8 + i;
        float* crow = g_XG + (size_t)row * GATES + bn + tx * 8;
#pragma unroll
        for (int j = 0; j < 8; j += 4) {
            float4 v;
            v.x = acc[i][j + 0] + bias[bn + tx * 8 + j + 0];
            v.y = acc[i][j + 1] + bias[bn + tx * 8 + j + 1];
            v.z = acc[i][j + 2] + bias[bn + tx * 8 + j + 2];
            v.w = acc[i][j + 3] + bias[bn + tx * 8 + j + 3];
            *(float4*)(crow + j) = v;
        }
    }
}

// ---------------- LSTM step: gates = XG[t] + h @ Wh; cell update ----------
// grid 128 blocks (8 hidden units each), 256 threads.
// thread: col c = tid&31 -> (u = c&7, gate = c>>3); rowgroup rg = tid>>5 (4 rows).
__global__ void lstm_step_kernel(const float* __restrict__ Wh, int t) {
    __shared__ float h_sc[64][33];     // [k][row], padded
    __shared__ float Ws[64 * 32];      // [k][col]
    __shared__ float gate_s[32 * 32];  // [row][col]

    const int tid = threadIdx.x;
    const int u0 = blockIdx.x * 8;
    const int c = tid & 31;
    const int rg = tid >> 5;
    const int u = c & 7, gsel = c >> 3;
    const int col = u0 + u + (gsel << 10);

    const float* __restrict__ h_in = g_h[t & 1];
    float* __restrict__ h_out = g_h[(t + 1) & 1];
    const float* __restrict__ XGt = g_XG + (size_t)t * BATCH * GATES;

    float acc0 = 0.f, acc1 = 0.f, acc2 = 0.f, acc3 = 0.f;

    for (int k0 = 0; k0 < HIDDEN; k0 += 64) {
        __syncthreads();
        // stage h chunk: 32 rows x 64 k
#pragma unroll
        for (int i = 0; i < 8; i++) {
            int idx = tid + i * 256;       // 0..2047
            int r = idx >> 6, kk = idx & 63;
            h_sc[kk][r] = h_in[r * HIDDEN + k0 + kk];
        }
        // stage W chunk: 64 k x 32 cols
#pragma unroll
        for (int i = 0; i < 8; i++) {
            int idx = tid + i * 256;
            int kk = idx >> 5, cc = idx & 31;
            int ccol = u0 + (cc & 7) + ((cc >> 3) << 10);
            Ws[idx] = Wh[(size_t)(k0 + kk) * GATES + ccol];
        }
        __syncthreads();
#pragma unroll
        for (int kk = 0; kk < 64; kk++) {
            float w = Ws[kk * 32 + c];
            const float* hr = &h_sc[kk][rg * 4];
            acc0 += hr[0] * w;
            acc1 += hr[1] * w;
            acc2 += hr[2] * w;
            acc3 += hr[3] * w;
        }
    }

    const int r0 = rg * 4;
    acc0 += XGt[(size_t)(r0 + 0) * GATES + col];
    acc1 += XGt[(size_t)(r0 + 1) * GATES + col];
    acc2 += XGt[(size_t)(r0 + 2) * GATES + col];
    acc3 += XGt[(size_t)(r0 + 3) * GATES + col];

    __syncthreads();
    gate_s[(r0 + 0) * 32 + c] = acc0;
    gate_s[(r0 + 1) * 32 + c] = acc1;
    gate_s[(r0 + 2) * 32 + c] = acc2;
    gate_s[(r0 + 3) * 32 + c] = acc3;
    __syncthreads();

    // pointwise cell update: (row r, unit uu)
    const int r = tid >> 3, uu = tid & 7;
    float ig = gate_s[r * 32 + uu];
    float fg = gate_s[r * 32 + 8 + uu];
    float gg = gate_s[r * 32 + 16 + uu];
    float og = gate_s[r * 32 + 24 + uu];
    const int unit = u0 + uu;

    float cold = g_c[r * HIDDEN + unit];
    float si = 1.0f / (1.0f + expf(-ig));
    float sf = 1.0f / (1.0f + expf(-fg));
    float so = 1.0f / (1.0f + expf(-og));
    float tg = tanhf(gg);
    float cn = sf * cold + si * tg;
    float hn = so * tanhf(cn);

    g_c[r * HIDDEN + unit] = cn;
    h_out[r * HIDDEN + unit] = hn;
    g_HS[((size_t)t * BATCH + r) * HIDDEN + unit] = hn;
}

// ---------------- GEMM 2: out = HS @ W_h2o + b_o (M=4096,N=32000,K=1024) --
__global__ void gemm_proj_kernel(const float* __restrict__ Wo,
                                 const float* __restrict__ bo,
                                 float* __restrict__ out) {
    __shared__ __align__(16) float As[8][128];
    __shared__ __align__(16) float Bs[8][128];

    const int tid = threadIdx.x;
    const int bm = blockIdx.y * 128;
    const int bn = blockIdx.x * 128;

    const int arow = tid >> 1;
    const int acol = (tid & 1) * 4;
    const int brow = tid >> 5;
    const int bcol = (tid & 31) * 4;
    const int tx = tid & 15, ty = tid >> 4;

    const float* Arow = g_HS + (size_t)(bm + arow) * HIDDEN;

    float acc[8][8];
#pragma unroll
    for (int i = 0; i < 8; i++)
#pragma unroll
        for (int j = 0; j < 8; j++) acc[i][j] = 0.0f;

    for (int k0 = 0; k0 < HIDDEN; k0 += 8) {
        float4 av = *(const float4*)(Arow + k0 + acol);
        As[acol + 0][arow] = av.x;
        As[acol + 1][arow] = av.y;
        As[acol + 2][arow] = av.z;
        As[acol + 3][arow] = av.w;
        float4 bv = *(const float4*)(Wo + (size_t)(k0 + brow) * NCLS + bn + bcol);
        *(float4*)&Bs[brow][bcol] = bv;
        __syncthreads();
#pragma unroll
        for (int kk = 0; kk < 8; kk++) {
            float a[8], b[8];
#pragma unroll
            for (int i = 0; i < 8; i++) a[i] = As[kk][ty * 8 + i];
#pragma unroll
            for (int j = 0; j < 8; j++) b[j] = Bs[kk][tx * 8 + j];
#pragma unroll
            for (int i = 0; i < 8; i++)
#pragma unroll
                for (int j = 0; j < 8; j++) acc[i][j] += a[i] * b[j];
        }
        __syncthreads();
    }

#pragma unroll
    for (int i = 0; i < 8; i++) {
        int row = bm + ty * 8 + i;
        float* crow = out + (size_t)row * NCLS + bn + tx * 8;
#pragma unroll
        for (int j = 0; j < 8; j += 4) {
            float4 v;
            v.x = acc[i][j + 0] + bo[bn + tx * 8 + j + 0];
            v.y = acc[i][j + 1] + bo[bn + tx * 8 + j + 1];
            v.z = acc[i][j + 2] + bo[bn + tx * 8 + j + 2];
            v.w = acc[i][j + 3] + bo[bn + tx * 8 + j + 3];
            *(float4*)(crow + j) = v;
        }
    }
}

// --------------------------------------------------------------------------
extern "C" void kernel_launch(void* const* d_in, const int* in_sizes, int n_in,
                              void* d_out, int out_size) {
    const int*   input = (const int*)d_in[0];    // [T,B] int32
    const float* emb   = (const float*)d_in[1];  // [32000,1024]
    const float* W_x   = (const float*)d_in[2];  // [1024,4096]
    const float* W_h   = (const float*)d_in[3];  // [1024,4096]
    const float* b     = (const float*)d_in[4];  // [4096]
    const float* W_h2o = (const float*)d_in[5];  // [1024,32000]
    const float* b_o   = (const float*)d_in[6];  // [32000]
    float* out = (float*)d_out;                  // [128,32,32000]

    (void)in_sizes; (void)n_in; (void)out_size;

    // zero h0 / c0
    init_state_kernel<<<(BATCH * HIDDEN + 255) / 256, 256>>>();

    // precompute XG = emb[ids] @ W_x + b for all (t,b)
    {
        dim3 grid(GATES / 128, M_ALL / 128);  // (32, 32)
        gemm_embed_kernel<<<grid, 256>>>(input, emb, W_x, b);
    }

    // sequential recurrence
    for (int t = 0; t < T_STEPS; t++) {
        lstm_step_kernel<<<128, 256>>>(W_h, t);
    }

    // readout projection
    {
        dim3 grid(NCLS / 128, M_ALL / 128);   // (250, 32)
        gemm_proj_kernel<<<grid, 256>>>(W_h2o, b_o, out);
    }
}

// round 7
// speedup vs baseline: 1.0506x; 1.0506x over previous
#include <cuda_runtime.h>
#include <math.h>

#define T_STEPS 128
#define BATCH   32
#define HIDDEN  1024
#define GATES   4096     // 4*HIDDEN
#define NCLS    32000
#define M_ALL   4096     // T_STEPS*BATCH
#define KSPLIT  4

// ---------------- scratch (device globals; no allocation) ----------------
__device__ float g_XG[(size_t)M_ALL * GATES];   // 64 MB
__device__ float g_HS[(size_t)M_ALL * HIDDEN];  // 16 MB
__device__ float g_h[2][BATCH * HIDDEN];
__device__ float g_c[BATCH * HIDDEN];
__device__ float g_part[KSPLIT * BATCH * GATES];

// ---------------- init ----------------
__global__ void init_state_kernel() {
    int i = blockIdx.x * blockDim.x + threadIdx.x;
    if (i < BATCH * HIDDEN) {
        g_h[0][i] = 0.0f;
        g_c[i] = 0.0f;
    }
}

// ---------------- GEMM 1 (R1-proven): XG = emb[ids] @ Wx + b ----------------
__global__ void gemm_embed_kernel(const int* __restrict__ ids,
                                  const float* __restrict__ emb,
                                  const float* __restrict__ Wx,
                                  const float* __restrict__ bias) {
    __shared__ __align__(16) float As[8][128];
    __shared__ __align__(16) float Bs[8][128];
    __shared__ int ids_s[128];

    const int tid = threadIdx.x;
    const int bm = blockIdx.y * 128;
    const int bn = blockIdx.x * 128;

    if (tid < 128) ids_s[tid] = ids[bm + tid];
    __syncthreads();

    const int arow = tid >> 1;
    const int acol = (tid & 1) * 4;
    const int brow = tid >> 5;
    const int bcol = (tid & 31) * 4;
    const int tx = tid & 15, ty = tid >> 4;

    const float* Arow = emb + (size_t)ids_s[arow] * HIDDEN;

    float acc[8][8];
#pragma unroll
    for (int i = 0; i < 8; i++)
#pragma unroll
        for (int j = 0; j < 8; j++) acc[i][j] = 0.0f;

    for (int k0 = 0; k0 < HIDDEN; k0 += 8) {
        float4 av = *(const float4*)(Arow + k0 + acol);
        As[acol + 0][arow] = av.x;
        As[acol + 1][arow] = av.y;
        As[acol + 2][arow] = av.z;
        As[acol + 3][arow] = av.w;
        float4 bv = *(const float4*)(Wx + (size_t)(k0 + brow) * GATES + bn + bcol);
        *(float4*)&Bs[brow][bcol] = bv;
        __syncthreads();
#pragma unroll
        for (int kk = 0; kk < 8; kk++) {
            float a[8], b[8];
#pragma unroll
            for (int i = 0; i < 8; i++) a[i] = As[kk][ty * 8 + i];
#pragma unroll
            for (int j = 0; j < 8; j++) b[j] = Bs[kk][tx * 8 + j];
#pragma unroll
            for (int i = 0; i < 8; i++)
#pragma unroll
                for (int j = 0; j < 8; j++) acc[i][j] += a[i] * b[j];
        }
        __syncthreads();
    }

#pragma unroll
    for (int i = 0; i < 8; i++) {
        int row = bm + ty * 8 + i;
        float* crow = g_XG + (size_t)row * GATES + bn + tx * 8;
#pragma unroll
        for (int j = 0; j < 8; j += 4) {
            float4 v;
            v.x = acc[i][j + 0] + bias[bn + tx * 8 + j + 0];
            v.y = acc[i][j + 1] + bias[bn + tx * 8 + j + 1];
            v.z = acc[i][j + 2] + bias[bn + tx * 8 + j + 2];
            v.w = acc[i][j + 3] + bias[bn + tx * 8 + j + 3];
            *(float4*)(crow + j) = v;
        }
    }
}

// ---------------- LSTM: K-split partial GEMM + reduce/pointwise ----------------
__global__ void lstm_gemm_kernel(const float* __restrict__ Wh, int t) {
    __shared__ float h_sc[64][33];
    __shared__ float Ws[64 * 32];

    const int tid = threadIdx.x;
    const int u0 = blockIdx.x * 8;
    const int ks = blockIdx.y;
    const int kbase = ks * (HIDDEN / KSPLIT);
    const int c = tid & 31;
    const int rg = tid >> 5;
    const int u = c & 7, gsel = c >> 3;
    const int col = u0 + u + (gsel << 10);

    const float* __restrict__ h_in = g_h[t & 1];

    float acc0 = 0.f, acc1 = 0.f, acc2 = 0.f, acc3 = 0.f;

    for (int k0 = kbase; k0 < kbase + HIDDEN / KSPLIT; k0 += 64) {
        __syncthreads();
#pragma unroll
        for (int i = 0; i < 8; i++) {
            int idx = tid + i * 256;
            int r = idx >> 6, kk = idx & 63;
            h_sc[kk][r] = h_in[r * HIDDEN + k0 + kk];
        }
#pragma unroll
        for (int i = 0; i < 8; i++) {
            int idx = tid + i * 256;
            int kk = idx >> 5, cc = idx & 31;
            int ccol = u0 + (cc & 7) + ((cc >> 3) << 10);
            Ws[idx] = Wh[(size_t)(k0 + kk) * GATES + ccol];
        }
        __syncthreads();
#pragma unroll
        for (int kk = 0; kk < 64; kk++) {
            float w = Ws[kk * 32 + c];
            const float* hr = &h_sc[kk][rg * 4];
            acc0 += hr[0] * w;
            acc1 += hr[1] * w;
            acc2 += hr[2] * w;
            acc3 += hr[3] * w;
        }
    }
    const int r0 = rg * 4;
    g_part[(size_t)(ks * BATCH + r0 + 0) * GATES + col] = acc0;
    g_part[(size_t)(ks * BATCH + r0 + 1) * GATES + col] = acc1;
    g_part[(size_t)(ks * BATCH + r0 + 2) * GATES + col] = acc2;
    g_part[(size_t)(ks * BATCH + r0 + 3) * GATES + col] = acc3;
}

__global__ void lstm_reduce_kernel(int t) {
    const int idx = blockIdx.x * 256 + threadIdx.x;
    const int unit = idx & (HIDDEN - 1);
    const int r = idx >> 10;

    const float* __restrict__ XGt = g_XG + (size_t)t * BATCH * GATES + (size_t)r * GATES;
    float gate[4];
#pragma unroll
    for (int g = 0; g < 4; g++) {
        const int col = unit + (g << 10);
        float s = XGt[col];
#pragma unroll
        for (int k = 0; k < KSPLIT; k++)
            s += g_part[(size_t)(k * BATCH + r) * GATES + col];
        gate[g] = s;
    }
    float cold = g_c[r * HIDDEN + unit];
    float si = 1.0f / (1.0f + expf(-gate[0]));
    float sf = 1.0f / (1.0f + expf(-gate[1]));
    float tg = tanhf(gate[2]);
    float so = 1.0f / (1.0f + expf(-gate[3]));
    float cn = sf * cold + si * tg;
    float hn = so * tanhf(cn);

    g_c[r * HIDDEN + unit] = cn;
    g_h[(t + 1) & 1][r * HIDDEN + unit] = hn;
    g_HS[((size_t)t * BATCH + r) * HIDDEN + unit] = hn;
}

// ---------------- GEMM 2 (R1-proven): out = HS @ W_h2o + b_o ----------------
__global__ void gemm_proj_kernel(const float* __restrict__ Wo,
                                 const float* __restrict__ bo,
                                 float* __restrict__ out) {
    __shared__ __align__(16) float As[8][128];
    __shared__ __align__(16) float Bs[8][128];

    const int tid = threadIdx.x;
    const int bm = blockIdx.y * 128;
    const int bn = blockIdx.x * 128;

    const int arow = tid >> 1;
    const int acol = (tid & 1) * 4;
    const int brow = tid >> 5;
    const int bcol = (tid & 31) * 4;
    const int tx = tid & 15, ty = tid >> 4;

    const float* Arow = g_HS + (size_t)(bm + arow) * HIDDEN;

    float acc[8][8];
#pragma unroll
    for (int i = 0; i < 8; i++)
#pragma unroll
        for (int j = 0; j < 8; j++) acc[i][j] = 0.0f;

    for (int k0 = 0; k0 < HIDDEN; k0 += 8) {
        float4 av = *(const float4*)(Arow + k0 + acol);
        As[acol + 0][arow] = av.x;
        As[acol + 1][arow] = av.y;
        As[acol + 2][arow] = av.z;
        As[acol + 3][arow] = av.w;
        float4 bv = *(const float4*)(Wo + (size_t)(k0 + brow) * NCLS + bn + bcol);
        *(float4*)&Bs[brow][bcol] = bv;
        __syncthreads();
#pragma unroll
        for (int kk = 0; kk < 8; kk++) {
            float a[8], b[8];
#pragma unroll
            for (int i = 0; i < 8; i++) a[i] = As[kk][ty * 8 + i];
#pragma unroll
            for (int j = 0; j < 8; j++) b[j] = Bs[kk][tx * 8 + j];
#pragma unroll
            for (int i = 0; i < 8; i++)
#pragma unroll
                for (int j = 0; j < 8; j++) acc[i][j] += a[i] * b[j];
        }
        __syncthreads();
    }

#pragma unroll
    for (int i = 0; i < 8; i++) {
        int row = bm + ty * 8 + i;
        float* crow = out + (size_t)row * NCLS + bn + tx * 8;
#pragma unroll
        for (int j = 0; j < 8; j += 4) {
            float4 v;
            v.x = acc[i][j + 0] + bo[bn + tx * 8 + j + 0];
            v.y = acc[i][j + 1] + bo[bn + tx * 8 + j + 1];
            v.z = acc[i][j + 2] + bo[bn + tx * 8 + j + 2];
            v.w = acc[i][j + 3] + bo[bn + tx * 8 + j + 3];
            *(float4*)(crow + j) = v;
        }
    }
}

// --------------------------------------------------------------------------
extern "C" void kernel_launch(void* const* d_in, const int* in_sizes, int n_in,
                              void* d_out, int out_size) {
    const int*   input = (const int*)d_in[0];
    const float* emb   = (const float*)d_in[1];
    const float* W_x   = (const float*)d_in[2];
    const float* W_h   = (const float*)d_in[3];
    const float* b     = (const float*)d_in[4];
    const float* W_h2o = (const float*)d_in[5];
    const float* b_o   = (const float*)d_in[6];
    float* out = (float*)d_out;

    (void)in_sizes; (void)n_in; (void)out_size;

    init_state_kernel<<<(BATCH * HIDDEN + 255) / 256, 256>>>();

    {
        dim3 grid(GATES / 128, M_ALL / 128);  // (32, 32)
        gemm_embed_kernel<<<grid, 256>>>(input, emb, W_x, b);
    }

    for (int t = 0; t < T_STEPS; t++) {
        dim3 gg(GATES / 32, KSPLIT);          // (128, 4)
        lstm_gemm_kernel<<<gg, 256>>>(W_h, t);
        lstm_reduce_kernel<<<128, 256>>>(t);
    }

    {
        dim3 grid(NCLS / 128, M_ALL / 128);   // (250, 32)
        gemm_proj_kernel<<<grid, 256>>>(W_h2o, b_o, out);
    }
}

// round 8
// speedup vs baseline: 1.5175x; 1.4444x over previous
#include <cuda_runtime.h>
#include <cuda_bf16.h>
#include <mma.h>
#include <math.h>

using namespace nvcuda;

#define T_STEPS 128
#define BATCH   32
#define HIDDEN  1024
#define GATES   4096     // 4*HIDDEN
#define NCLS    32000
#define M_ALL   4096     // T_STEPS*BATCH
#define KSPLIT  4

// ---------------- scratch ----------------
__device__ float g_XG[(size_t)M_ALL * GATES];   // 64 MB
__device__ float g_HS[(size_t)M_ALL * HIDDEN];  // 16 MB
__device__ float g_h[2][BATCH * HIDDEN];
__device__ float g_c[BATCH * HIDDEN];
__device__ float g_part[KSPLIT * BATCH * GATES];

// ---------------- init ----------------
__global__ void init_state_kernel() {
    int i = blockIdx.x * blockDim.x + threadIdx.x;
    if (i < BATCH * HIDDEN) {
        g_h[0][i] = 0.0f;
        g_c[i] = 0.0f;
    }
}

// ---------------- GEMM 1 (R1-proven): XG = emb[ids] @ Wx + b ----------------
__global__ void gemm_embed_kernel(const int* __restrict__ ids,
                                  const float* __restrict__ emb,
                                  const float* __restrict__ Wx,
                                  const float* __restrict__ bias) {
    __shared__ __align__(16) float As[8][128];
    __shared__ __align__(16) float Bs[8][128];
    __shared__ int ids_s[128];

    const int tid = threadIdx.x;
    const int bm = blockIdx.y * 128;
    const int bn = blockIdx.x * 128;

    if (tid < 128) ids_s[tid] = ids[bm + tid];
    __syncthreads();

    const int arow = tid >> 1;
    const int acol = (tid & 1) * 4;
    const int brow = tid >> 5;
    const int bcol = (tid & 31) * 4;
    const int tx = tid & 15, ty = tid >> 4;

    const float* Arow = emb + (size_t)ids_s[arow] * HIDDEN;

    float acc[8][8];
#pragma unroll
    for (int i = 0; i < 8; i++)
#pragma unroll
        for (int j = 0; j < 8; j++) acc[i][j] = 0.0f;

    for (int k0 = 0; k0 < HIDDEN; k0 += 8) {
        float4 av = *(const float4*)(Arow + k0 + acol);
        As[acol + 0][arow] = av.x;
        As[acol + 1][arow] = av.y;
        As[acol + 2][arow] = av.z;
        As[acol + 3][arow] = av.w;
        float4 bv = *(const float4*)(Wx + (size_t)(k0 + brow) * GATES + bn + bcol);
        *(float4*)&Bs[brow][bcol] = bv;
        __syncthreads();
#pragma unroll
        for (int kk = 0; kk < 8; kk++) {
            float a[8], b[8];
#pragma unroll
            for (int i = 0; i < 8; i++) a[i] = As[kk][ty * 8 + i];
#pragma unroll
            for (int j = 0; j < 8; j++) b[j] = Bs[kk][tx * 8 + j];
#pragma unroll
            for (int i = 0; i < 8; i++)
#pragma unroll
                for (int j = 0; j < 8; j++) acc[i][j] += a[i] * b[j];
        }
        __syncthreads();
    }

#pragma unroll
    for (int i = 0; i < 8; i++) {
        int row = bm + ty * 8 + i;
        float* crow = g_XG + (size_t)row * GATES + bn + tx * 8;
#pragma unroll
        for (int j = 0; j < 8; j += 4) {
            float4 v;
            v.x = acc[i][j + 0] + bias[bn + tx * 8 + j + 0];
            v.y = acc[i][j + 1] + bias[bn + tx * 8 + j + 1];
            v.z = acc[i][j + 2] + bias[bn + tx * 8 + j + 2];
            v.w = acc[i][j + 3] + bias[bn + tx * 8 + j + 3];
            *(float4*)(crow + j) = v;
        }
    }
}

// ---------------- LSTM: K-split partial GEMM + reduce/pointwise (R7-proven) ----
__global__ void lstm_gemm_kernel(const float* __restrict__ Wh, int t) {
    __shared__ float h_sc[64][33];
    __shared__ float Ws[64 * 32];

    const int tid = threadIdx.x;
    const int u0 = blockIdx.x * 8;
    const int ks = blockIdx.y;
    const int kbase = ks * (HIDDEN / KSPLIT);
    const int c = tid & 31;
    const int rg = tid >> 5;
    const int u = c & 7, gsel = c >> 3;
    const int col = u0 + u + (gsel << 10);

    const float* __restrict__ h_in = g_h[t & 1];

    float acc0 = 0.f, acc1 = 0.f, acc2 = 0.f, acc3 = 0.f;

    for (int k0 = kbase; k0 < kbase + HIDDEN / KSPLIT; k0 += 64) {
        __syncthreads();
#pragma unroll
        for (int i = 0; i < 8; i++) {
            int idx = tid + i * 256;
            int r = idx >> 6, kk = idx & 63;
            h_sc[kk][r] = h_in[r * HIDDEN + k0 + kk];
        }
#pragma unroll
        for (int i = 0; i < 8; i++) {
            int idx = tid + i * 256;
            int kk = idx >> 5, cc = idx & 31;
            int ccol = u0 + (cc & 7) + ((cc >> 3) << 10);
            Ws[idx] = Wh[(size_t)(k0 + kk) * GATES + ccol];
        }
        __syncthreads();
#pragma unroll
        for (int kk = 0; kk < 64; kk++) {
            float w = Ws[kk * 32 + c];
            const float* hr = &h_sc[kk][rg * 4];
            acc0 += hr[0] * w;
            acc1 += hr[1] * w;
            acc2 += hr[2] * w;
            acc3 += hr[3] * w;
        }
    }
    const int r0 = rg * 4;
    g_part[(size_t)(ks * BATCH + r0 + 0) * GATES + col] = acc0;
    g_part[(size_t)(ks * BATCH + r0 + 1) * GATES + col] = acc1;
    g_part[(size_t)(ks * BATCH + r0 + 2) * GATES + col] = acc2;
    g_part[(size_t)(ks * BATCH + r0 + 3) * GATES + col] = acc3;
}

__global__ void lstm_reduce_kernel(int t) {
    const int idx = blockIdx.x * 256 + threadIdx.x;
    const int unit = idx & (HIDDEN - 1);
    const int r = idx >> 10;

    const float* __restrict__ XGt = g_XG + (size_t)t * BATCH * GATES + (size_t)r * GATES;
    float gate[4];
#pragma unroll
    for (int g = 0; g < 4; g++) {
        const int col = unit + (g << 10);
        float s = XGt[col];
#pragma unroll
        for (int k = 0; k < KSPLIT; k++)
            s += g_part[(size_t)(k * BATCH + r) * GATES + col];
        gate[g] = s;
    }
    float cold = g_c[r * HIDDEN + unit];
    float si = 1.0f / (1.0f + expf(-gate[0]));
    float sf = 1.0f / (1.0f + expf(-gate[1]));
    float tg = tanhf(gate[2]);
    float so = 1.0f / (1.0f + expf(-gate[3]));
    float cn = sf * cold + si * tg;
    float hn = so * tanhf(cn);

    g_c[r * HIDDEN + unit] = cn;
    g_h[(t + 1) & 1][r * HIDDEN + unit] = hn;
    g_HS[((size_t)t * BATCH + r) * HIDDEN + unit] = hn;
}

// ---------------- GEMM 2: wmma bf16 hi/lo  out = HS @ Wo + bo ----------------
// CTA 128x128, BK=32. 256 threads = 8 warps (2M x 4N); warp 64x32 = 4x2 frags.
// HS fp32 [M][K] row-major -> matrix_a row_major; Wo fp32 [K][N] -> matrix_b row_major.
// fp32 -> bf16 hi/lo conversion done in-kernel while staging to smem.
#define PBK   32
#define ASTR  40      // A smem row stride (elements); 80B, mult of 16B
#define BSTR  136     // B smem row stride (elements); 272B, mult of 16B

__global__ void __launch_bounds__(256, 1)
gemm_wmma_proj(const float* __restrict__ Wo, const float* __restrict__ bo,
               float* __restrict__ out) {
    __shared__ __align__(128) __nv_bfloat16 sAh[128 * ASTR];   // 10240 B
    __shared__ __align__(128) __nv_bfloat16 sAl[128 * ASTR];   // 10240 B
    __shared__ __align__(128) __nv_bfloat16 sBh[PBK * BSTR];   //  8704 B
    __shared__ __align__(128) __nv_bfloat16 sBl[PBK * BSTR];   //  8704 B
    __shared__ __align__(128) float sbias[16 * BSTR];          //  8704 B  => total 46592

    const int tid = threadIdx.x;
    const int wid = tid >> 5;
    const int bn = blockIdx.x * 128;
    const int bm = blockIdx.y * 128;
    const int wm = wid & 1;    // 0..1
    const int wn = wid >> 1;   // 0..3

    // build replicated bias tile (16 rows x 128 cols)
    if (tid < 128) {
        float bv = bo[bn + tid];
#pragma unroll
        for (int r = 0; r < 16; r++) sbias[r * BSTR + tid] = bv;
    }
    __syncthreads();

    // accumulators initialized with bias
    wmma::fragment<wmma::accumulator, 16, 16, 16, float> acc[4][2];
#pragma unroll
    for (int mi = 0; mi < 4; mi++)
#pragma unroll
        for (int ni = 0; ni < 2; ni++)
            wmma::load_matrix_sync(acc[mi][ni], sbias + wn * 32 + ni * 16, BSTR,
                                   wmma::mem_row_major);

    // per-thread load coordinates
    const int a_r = tid >> 3;            // 0..31 (row within 32-row sweep)
    const int a_c = (tid & 7) * 4;       // 0..28
    const int b_r = tid >> 5;            // 0..7  (row within 8-row sweep)
    const int b_c = (tid & 31) * 4;      // 0..124

    // prefetch chunk 0
    float ra[4][4], rb[4][4];
#pragma unroll
    for (int s = 0; s < 4; s++) {
        *(float4*)ra[s] = *(const float4*)(g_HS + (size_t)(bm + s * 32 + a_r) * HIDDEN + a_c);
        *(float4*)rb[s] = *(const float4*)(Wo + (size_t)(s * 8 + b_r) * NCLS + bn + b_c);
    }

    const int NCHUNK = HIDDEN / PBK;   // 32
#pragma unroll 1
    for (int i = 0; i < NCHUNK; i++) {
        // store current chunk (convert fp32 -> bf16 hi/lo)
#pragma unroll
        for (int s = 0; s < 4; s++) {
            int arow = s * 32 + a_r;
#pragma unroll
            for (int j = 0; j < 4; j++) {
                float v = ra[s][j];
                __nv_bfloat16 h = __float2bfloat16(v);
                sAh[arow * ASTR + a_c + j] = h;
                sAl[arow * ASTR + a_c + j] = __float2bfloat16(v - __bfloat162float(h));
            }
            int brow = s * 8 + b_r;
#pragma unroll
            for (int j = 0; j < 4; j++) {
                float v = rb[s][j];
                __nv_bfloat16 h = __float2bfloat16(v);
                sBh[brow * BSTR + b_c + j] = h;
                sBl[brow * BSTR + b_c + j] = __float2bfloat16(v - __bfloat162float(h));
            }
        }
        __syncthreads();

        // prefetch next chunk (overlaps with wmma below)
        if (i + 1 < NCHUNK) {
            int k0 = (i + 1) * PBK;
#pragma unroll
            for (int s = 0; s < 4; s++) {
                *(float4*)ra[s] = *(const float4*)(g_HS + (size_t)(bm + s * 32 + a_r) * HIDDEN + k0 + a_c);
                *(float4*)rb[s] = *(const float4*)(Wo + (size_t)(k0 + s * 8 + b_r) * NCLS + bn + b_c);
            }
        }

        // compute on smem chunk
#pragma unroll
        for (int kk = 0; kk < 2; kk++) {
            wmma::fragment<wmma::matrix_a, 16, 16, 16, __nv_bfloat16, wmma::row_major> afh[4], afl[4];
            wmma::fragment<wmma::matrix_b, 16, 16, 16, __nv_bfloat16, wmma::row_major> bfh[2], bfl[2];
#pragma unroll
            for (int mi = 0; mi < 4; mi++) {
                const __nv_bfloat16* ap = sAh + (wm * 64 + mi * 16) * ASTR + kk * 16;
                wmma::load_matrix_sync(afh[mi], ap, ASTR);
                wmma::load_matrix_sync(afl[mi], ap + 128 * ASTR * 0 + (sAl - sAh), ASTR);
            }
#pragma unroll
            for (int ni = 0; ni < 2; ni++) {
                const __nv_bfloat16* bp = sBh + (kk * 16) * BSTR + wn * 32 + ni * 16;
                wmma::load_matrix_sync(bfh[ni], bp, BSTR);
                wmma::load_matrix_sync(bfl[ni], bp + (sBl - sBh), BSTR);
            }
#pragma unroll
            for (int mi = 0; mi < 4; mi++)
#pragma unroll
                for (int ni = 0; ni < 2; ni++) {
                    wmma::mma_sync(acc[mi][ni], afh[mi], bfh[ni], acc[mi][ni]);
                    wmma::mma_sync(acc[mi][ni], afh[mi], bfl[ni], acc[mi][ni]);
                    wmma::mma_sync(acc[mi][ni], afl[mi], bfh[ni], acc[mi][ni]);
                }
        }
        __syncthreads();
    }

    // epilogue: direct wmma stores (bias already inside acc)
#pragma unroll
    for (int mi = 0; mi < 4; mi++)
#pragma unroll
        for (int ni = 0; ni < 2; ni++) {
            float* op = out + (size_t)(bm + wm * 64 + mi * 16) * NCLS + bn + wn * 32 + ni * 16;
            wmma::store_matrix_sync(op, acc[mi][ni], NCLS, wmma::mem_row_major);
        }
}

// --------------------------------------------------------------------------
extern "C" void kernel_launch(void* const* d_in, const int* in_sizes, int n_in,
                              void* d_out, int out_size) {
    const int*   input = (const int*)d_in[0];
    const float* emb   = (const float*)d_in[1];
    const float* W_x   = (const float*)d_in[2];
    const float* W_h   = (const float*)d_in[3];
    const float* b     = (const float*)d_in[4];
    const float* W_h2o = (const float*)d_in[5];
    const float* b_o   = (const float*)d_in[6];
    float* out = (float*)d_out;

    (void)in_sizes; (void)n_in; (void)out_size;

    init_state_kernel<<<(BATCH * HIDDEN + 255) / 256, 256>>>();

    {
        dim3 grid(GATES / 128, M_ALL / 128);  // (32, 32)
        gemm_embed_kernel<<<grid, 256>>>(input, emb, W_x, b);
    }

    for (int t = 0; t < T_STEPS; t++) {
        dim3 gg(GATES / 32, KSPLIT);          // (128, 4)
        lstm_gemm_kernel<<<gg, 256>>>(W_h, t);
        lstm_reduce_kernel<<<128, 256>>>(t);
    }

    {
        dim3 grid(NCLS / 128, M_ALL / 128);   // (250, 32)
        gemm_wmma_proj<<<grid, 256>>>(W_h2o, b_o, out);
    }
}